// round 11
// baseline (speedup 1.0000x reference)
#include <cuda_runtime.h>

#define BB 32
#define TT 512
#define UU 512
#define NG 1536          // 3*U
#define OC 1024          // 2*U output channels
#define CPB 4            // columns per scan block
#define BPD 128          // scan blocks per direction
#define NLEAF 16         // barrier tree leaves per direction (8 blocks each)

// x-gates scratch: [dir][B*T][3U] fp32 (192 MB, static device allocation)
__device__ float    g_xg[(size_t)2 * BB * TT * NG];
// per-step rh = r * h_prev exchange buffer
__device__ float    g_rh[2 * BB * UU];
// tree barrier state: counters padded to 256B-distinct addresses
__device__ int      g_leaf[2 * NLEAF * 64];
__device__ int      g_root[2 * 64];
__device__ unsigned g_gen [2 * 64];

__device__ __forceinline__ float hsig(float v) {
    return fminf(fmaxf(0.2f * v + 0.5f, 0.0f), 1.0f);
}

// packed dual-FMA: acc.{lo,hi} += a.{lo,hi} * b.{lo,hi}
#define FMA2(acc, a, b) \
    asm("fma.rn.f32x2 %0, %1, %2, %0;" : "+l"(acc) : "l"(a), "l"(b))

__device__ __forceinline__ float pair_sum(unsigned long long v) {
    return __uint_as_float((unsigned)v) + __uint_as_float((unsigned)(v >> 32));
}

// ---------------------------------------------------------------------------
// Phase 1: Xg[dir][m][n] = x[m][:] @ W_dir[:][n] + bias_dir[n]
// M=16384, K=512, N=1536. BM=BN=128, BK=16, 256 thr, 8x8 reg tile,
// register-prefetch double buffering. (verified r7-r10)
// ---------------------------------------------------------------------------
#define XS 132           // padded smem row stride (floats)

__global__ void __launch_bounds__(256, 2)
xgemm_kernel(const float* __restrict__ A,
             const float* __restrict__ Wf, const float* __restrict__ bf,
             const float* __restrict__ Wb, const float* __restrict__ bb)
{
    const int dir = blockIdx.z;
    const float* __restrict__ W    = dir ? Wb : Wf;
    const float* __restrict__ bias = dir ? bb : bf;
    const int m0 = blockIdx.y * 128;
    const int n0 = blockIdx.x * 128;

    __shared__ float As[16 * XS];   // [k][m]
    __shared__ float Bs[16 * XS];   // [k][n]

    const int tid = threadIdx.x;
    const int tx = tid & 15;        // n group (8 cols)
    const int ty = tid >> 4;        // m group (8 rows)

    const int arow = tid >> 1;             // 0..127
    const int akq  = (tid & 1) << 3;       // 0 or 8
    const int bk = tid >> 4;               // 0..15
    const int bn = (tid & 15) << 3;        // 0..120

    const float* Aptr = A + (size_t)(m0 + arow) * 512 + akq;
    const float* Wptr = W + (size_t)bk * NG + n0 + bn;

    float acc[8][8];
#pragma unroll
    for (int i = 0; i < 8; ++i)
#pragma unroll
        for (int j = 0; j < 8; ++j) acc[i][j] = 0.0f;

    float4 a0 = *(const float4*)(Aptr + 0);
    float4 a1 = *(const float4*)(Aptr + 4);
    float4 b0 = *(const float4*)(Wptr + 0);
    float4 b1 = *(const float4*)(Wptr + 4);

    {
        float av[8] = {a0.x,a0.y,a0.z,a0.w,a1.x,a1.y,a1.z,a1.w};
#pragma unroll
        for (int j = 0; j < 8; ++j) As[(akq + j) * XS + arow] = av[j];
        *(float4*)&Bs[bk * XS + bn]     = b0;
        *(float4*)&Bs[bk * XS + bn + 4] = b1;
    }
    __syncthreads();

    for (int kt = 0; kt < 32; ++kt) {
        const int k_next = (kt + 1) << 4;
        if (kt < 31) {
            a0 = *(const float4*)(Aptr + k_next + 0);
            a1 = *(const float4*)(Aptr + k_next + 4);
            b0 = *(const float4*)(Wptr + (size_t)k_next * NG + 0);
            b1 = *(const float4*)(Wptr + (size_t)k_next * NG + 4);
        }

#pragma unroll
        for (int kk = 0; kk < 16; ++kk) {
            float4 av0 = *(const float4*)&As[kk * XS + ty * 8];
            float4 av1 = *(const float4*)&As[kk * XS + ty * 8 + 4];
            float4 bv0 = *(const float4*)&Bs[kk * XS + tx * 8];
            float4 bv1 = *(const float4*)&Bs[kk * XS + tx * 8 + 4];
            float aa[8]  = {av0.x,av0.y,av0.z,av0.w,av1.x,av1.y,av1.z,av1.w};
            float bb2[8] = {bv0.x,bv0.y,bv0.z,bv0.w,bv1.x,bv1.y,bv1.z,bv1.w};
#pragma unroll
            for (int i = 0; i < 8; ++i)
#pragma unroll
                for (int j = 0; j < 8; ++j)
                    acc[i][j] = fmaf(aa[i], bb2[j], acc[i][j]);
        }

        if (kt < 31) {
            __syncthreads();
            float av[8] = {a0.x,a0.y,a0.z,a0.w,a1.x,a1.y,a1.z,a1.w};
#pragma unroll
            for (int j = 0; j < 8; ++j) As[(akq + j) * XS + arow] = av[j];
            *(float4*)&Bs[bk * XS + bn]     = b0;
            *(float4*)&Bs[bk * XS + bn + 4] = b1;
            __syncthreads();
        }
    }

    float* __restrict__ Cd = g_xg + (size_t)dir * BB * TT * NG;
    const int nbase = n0 + tx * 8;
    float4 bi0 = *(const float4*)(bias + nbase);
    float4 bi1 = *(const float4*)(bias + nbase + 4);
#pragma unroll
    for (int i = 0; i < 8; ++i) {
        const int m = m0 + ty * 8 + i;
        float4 o0, o1;
        o0.x = acc[i][0] + bi0.x; o0.y = acc[i][1] + bi0.y;
        o0.z = acc[i][2] + bi0.z; o0.w = acc[i][3] + bi0.w;
        o1.x = acc[i][4] + bi1.x; o1.y = acc[i][5] + bi1.y;
        o1.z = acc[i][6] + bi1.z; o1.w = acc[i][7] + bi1.w;
        *(float4*)&Cd[(size_t)m * NG + nbase]     = o0;
        *(float4*)&Cd[(size_t)m * NG + nbase + 4] = o1;
    }
}

// ---------------------------------------------------------------------------
// Two-level tree grid barrier per direction: 128 blocks = 16 leaves x 8.
// Generation-based release (survives graph replays).
// ---------------------------------------------------------------------------
__device__ __forceinline__ void grid_bar(int dir, int leaf, int tid,
                                         unsigned& bar_t)
{
    __threadfence();                       // release global writes
    __syncthreads();                       // all threads' writes fenced
    if (tid == 0) {
        ++bar_t;                           // target generation
        bool released = false;
        if (atomicAdd(&g_leaf[(dir * NLEAF + leaf) << 6], 1) == 7) {
            atomicExch(&g_leaf[(dir * NLEAF + leaf) << 6], 0);
            if (atomicAdd(&g_root[dir << 6], 1) == NLEAF - 1) {
                atomicExch(&g_root[dir << 6], 0);
                __threadfence();
                atomicExch(&g_gen[dir << 6], bar_t);
                released = true;
            }
        }
        if (!released) {
            while ((int)(*(volatile unsigned*)&g_gen[dir << 6] - bar_t) < 0) { }
            __threadfence();               // acquire
        }
    }
    __syncthreads();
}

// ---------------------------------------------------------------------------
// Phase 2: persistent scan. 256 blocks x 256 threads, TWO blocks per SM.
// Block = (dir, 4 cols). Thread = (ks in 0..1, b in 0..31, c in 0..3):
// K half (256) per thread, float4/FFMA2 inner loops, 2-way smem reduction.
// smem floats: sW 12*516=6192 | sH 32*516=16512 | red 512  -> 92,864 B/block
// ---------------------------------------------------------------------------
#define SWS 516
#define SCAN_SMEM_FLOATS (12 * SWS + BB * SWS + 512)
#define SCAN_SMEM_BYTES  (SCAN_SMEM_FLOATS * 4)

__global__ void __launch_bounds__(256, 2)
scan_kernel(const float* __restrict__ Uf,
            const float* __restrict__ Ub,
            float* __restrict__ out)
{
    extern __shared__ float sm[];
    float* sW  = sm;                   // [g][c][u] : (g*4 + c)*516 + u
    float* sH  = sm + 12 * SWS;        // [b][u]    : b*516 + u
    float* red = sH + BB * SWS;        // [ks][b][c][g] : ks*256 + b*8 + c*2 + g

    const int tid   = threadIdx.x;
    const int dir   = blockIdx.x >> 7;
    const int cg    = blockIdx.x & 127;
    const int leaf  = cg >> 3;
    const int hbase = cg * CPB;
    const float* __restrict__ Urec = dir ? Ub : Uf;

    // --- weight slices, loaded ONCE: sW[(g*4+c)*516 + u] = Urec[u][g*512+hbase+c]
    for (int i = tid; i < 3 * CPB * UU; i += 256) {
        const int u  = i >> 4;           // wait: 3*4=12 combos -> i = u*12+gc
        const int gc = i - u * 12;       // not a power of 2; recompute cleanly
        (void)gc;
        break;                           // replaced by loop below
    }
    // clean version: iterate u outer, gc inner
    for (int i = tid; i < UU * 12; i += 256) {
        const int u  = i / 12;
        const int gc = i % 12;
        const int g  = gc >> 2;          // 0..2
        const int c  = gc & 3;           // 0..3
        sW[(g * CPB + c) * SWS + u] = Urec[(size_t)u * NG + g * UU + hbase + c];
    }

    unsigned bar_t = 0;
    if (tid == 0) bar_t = *(volatile unsigned*)&g_gen[dir << 6];

    // GEMM mapping
    const int ks = tid >> 7;             // 0..1  (K half)
    const int gb = (tid >> 2) & 31;      // 0..31 (batch)
    const int gc = tid & 3;              // 0..3  (column)
    const int u0 = ks << 8;              // 0 or 256
    // post-reduce mapping (tid < 128)
    const int rb = tid >> 2;             // 0..31
    const int rc = tid & 3;              // 0..3
    const int j  = hbase + rc;

    const ulonglong2* __restrict__ wz2 =
        (const ulonglong2*)(sW + (0 * CPB + gc) * SWS + u0);
    const ulonglong2* __restrict__ wr2 =
        (const ulonglong2*)(sW + (1 * CPB + gc) * SWS + u0);
    const ulonglong2* __restrict__ wh2 =
        (const ulonglong2*)(sW + (2 * CPB + gc) * SWS + u0);
    const ulonglong2* __restrict__ hv2 =
        (const ulonglong2*)(sH + gb * SWS + u0);

    const size_t xg_base = (size_t)dir * BB * TT + (size_t)rb * TT;
    const int    rh_base = (dir * BB) << 9;
    const size_t out_col = (size_t)dir * UU;

    __syncthreads();                     // weights ready

    float rz = 0.0f, rzh = 0.0f;

    for (int s = 0; s < TT; ++s) {
        // ---- x-gate prefetch (only meaningful for tid < 128) ----
        const int t_x = dir ? (TT - 1 - s) : s;
        const float* __restrict__ xrow = g_xg + (xg_base + t_x) * NG;
        float xz = 0.f, xr = 0.f, xh = 0.f;
        if (tid < 128) {
            xz = xrow[j];
            xr = xrow[UU + j];
            xh = xrow[2 * UU + j];
        }

        // ---- stage h_prev -> sH (16 float4/thread, two waves of 8) ----
        if (s == 0) {
            for (int i = tid; i < BB * SWS; i += 256) sH[i] = 0.0f;
        } else {
            const float* __restrict__ hsrc =
                out + (size_t)(s - 1) * OC + out_col;
            float4 t0[8], t1[8];
#pragma unroll
            for (int r = 0; r < 8; ++r) {
                const int i = tid + (r << 8);
                t0[r] = __ldcg((const float4*)(hsrc +
                         (size_t)(i >> 7) * TT * OC + ((i & 127) << 2)));
            }
#pragma unroll
            for (int r = 0; r < 8; ++r) {
                const int i = tid + (r << 8);
                *(float4*)&sH[(i >> 7) * SWS + ((i & 127) << 2)] = t0[r];
            }
#pragma unroll
            for (int r = 0; r < 8; ++r) {
                const int i = tid + ((r + 8) << 8);
                t1[r] = __ldcg((const float4*)(hsrc +
                         (size_t)(i >> 7) * TT * OC + ((i & 127) << 2)));
            }
#pragma unroll
            for (int r = 0; r < 8; ++r) {
                const int i = tid + ((r + 8) << 8);
                *(float4*)&sH[(i >> 7) * SWS + ((i & 127) << 2)] = t1[r];
            }
        }
        __syncthreads();

        // ---- phase A: z/r gates over K half ----
        unsigned long long az0 = 0ull, az1 = 0ull, ar0 = 0ull, ar1 = 0ull;
#pragma unroll 8
        for (int uu = 0; uu < 64; ++uu) {      // 64 x 4u = 256 u
            ulonglong2 hv = hv2[uu];
            ulonglong2 w1 = wz2[uu];
            ulonglong2 w2 = wr2[uu];
            FMA2(az0, hv.x, w1.x); FMA2(az1, hv.y, w1.y);
            FMA2(ar0, hv.x, w2.x); FMA2(ar1, hv.y, w2.y);
        }
        {
            float* rp = red + (ks << 8) + (gb << 3) + (gc << 1);
            rp[0] = pair_sum(az0) + pair_sum(az1);
            rp[1] = pair_sum(ar0) + pair_sum(ar1);
        }
        __syncthreads();

        if (tid < 128) {
            const int base = (rb << 3) + (rc << 1);
            const float hz = red[base]     + red[256 + base];
            const float hr = red[base + 1] + red[256 + base + 1];
            const float z  = hsig(xz + hz);
            const float r  = hsig(xr + hr);
            const float hp = sH[rb * SWS + j];
            rz  = z;
            rzh = z * hp;
            __stcg(&g_rh[rh_base + (rb << 9) + j], r * hp);
        }
        grid_bar(dir, leaf, tid, bar_t);

        // ---- stage rh -> sH (contiguous source) ----
        {
            const float* __restrict__ rsrc = g_rh + rh_base;
            float4 t0[8], t1[8];
#pragma unroll
            for (int r = 0; r < 8; ++r)
                t0[r] = __ldcg((const float4*)(rsrc + ((tid + (r << 8)) << 2)));
#pragma unroll
            for (int r = 0; r < 8; ++r) {
                const int i = tid + (r << 8);
                *(float4*)&sH[(i >> 7) * SWS + ((i & 127) << 2)] = t0[r];
            }
#pragma unroll
            for (int r = 0; r < 8; ++r)
                t1[r] = __ldcg((const float4*)(rsrc +
                                               ((tid + ((r + 8) << 8)) << 2)));
#pragma unroll
            for (int r = 0; r < 8; ++r) {
                const int i = tid + ((r + 8) << 8);
                *(float4*)&sH[(i >> 7) * SWS + ((i & 127) << 2)] = t1[r];
            }
        }
        __syncthreads();

        // ---- phase B: candidate GEMM over K half ----
        unsigned long long ah0 = 0ull, ah1 = 0ull;
#pragma unroll 8
        for (int uu = 0; uu < 64; ++uu) {
            ulonglong2 hv = hv2[uu];
            ulonglong2 w1 = wh2[uu];
            FMA2(ah0, hv.x, w1.x); FMA2(ah1, hv.y, w1.y);
        }
        {
            float* rp = red + (ks << 8) + (gb << 3) + (gc << 1);
            rp[0] = pair_sum(ah0) + pair_sum(ah1);
        }
        __syncthreads();

        if (tid < 128) {
            const int base = (rb << 3) + (rc << 1);
            const float hh   = red[base] + red[256 + base];
            const float cand = tanhf(xh + hh);
            const float hnew = rzh + (1.0f - rz) * cand;
            __stcg(&out[((size_t)rb * TT + s) * OC + out_col + j], hnew);
        }
        grid_bar(dir, leaf, tid, bar_t);
    }
}

// ---------------------------------------------------------------------------
extern "C" void kernel_launch(void* const* d_in, const int* in_sizes, int n_in,
                              void* d_out, int out_size)
{
    (void)in_sizes; (void)n_in; (void)out_size;
    const float* x  = (const float*)d_in[0];
    const float* Wf = (const float*)d_in[1];
    const float* Uf = (const float*)d_in[2];
    const float* bf = (const float*)d_in[3];
    const float* Wb = (const float*)d_in[4];
    const float* Ub = (const float*)d_in[5];
    const float* bb = (const float*)d_in[6];
    float* out = (float*)d_out;

    cudaFuncSetAttribute(scan_kernel,
                         cudaFuncAttributeMaxDynamicSharedMemorySize,
                         SCAN_SMEM_BYTES);

    dim3 g1(NG / 128, (BB * TT) / 128, 2);   // 12 x 128 x 2
    xgemm_kernel<<<g1, 256>>>(x, Wf, bf, Wb, bb);

    scan_kernel<<<2 * BPD, 256, SCAN_SMEM_BYTES>>>(Uf, Ub, out);
}

// round 12
// speedup vs baseline: 1.2861x; 1.2861x over previous
#include <cuda_runtime.h>

#define BB 32
#define TT 512
#define UU 512
#define NG 1536          // 3*U
#define OC 1024          // 2*U output channels

// x-gates scratch: [dir][B*T][3U] fp32 (192 MB, static device allocation)
__device__ float    g_xg[(size_t)2 * BB * TT * NG];
// per-step rh = r * h_prev exchange buffer
__device__ float    g_rh[2 * BB * UU];
// software grid barrier state (per direction)
__device__ unsigned g_cnt[2];
__device__ unsigned g_gen[2];

__device__ __forceinline__ float hsig(float v) {
    return fminf(fmaxf(0.2f * v + 0.5f, 0.0f), 1.0f);
}

// ---------------------------------------------------------------------------
// Phase 1: Xg[dir][m][n] = x[m][:] @ W_dir[:][n] + bias_dir[n]
// M=16384, K=512, N=1536. BM=BN=128, BK=16, 256 thr, 8x8 reg tile,
// register-prefetch double buffering. (isolated win, ~0.65 ms vs r5 xgemm)
// ---------------------------------------------------------------------------
#define XS 132           // padded smem row stride (floats)

__global__ void __launch_bounds__(256, 2)
xgemm_kernel(const float* __restrict__ A,
             const float* __restrict__ Wf, const float* __restrict__ bf,
             const float* __restrict__ Wb, const float* __restrict__ bb)
{
    const int dir = blockIdx.z;
    const float* __restrict__ W    = dir ? Wb : Wf;
    const float* __restrict__ bias = dir ? bb : bf;
    const int m0 = blockIdx.y * 128;
    const int n0 = blockIdx.x * 128;

    __shared__ float As[16 * XS];   // [k][m]
    __shared__ float Bs[16 * XS];   // [k][n]

    const int tid = threadIdx.x;
    const int tx = tid & 15;        // n group (8 cols)
    const int ty = tid >> 4;        // m group (8 rows)

    const int arow = tid >> 1;             // 0..127
    const int akq  = (tid & 1) << 3;       // 0 or 8
    const int bk = tid >> 4;               // 0..15
    const int bn = (tid & 15) << 3;        // 0..120

    const float* Aptr = A + (size_t)(m0 + arow) * 512 + akq;
    const float* Wptr = W + (size_t)bk * NG + n0 + bn;

    float acc[8][8];
#pragma unroll
    for (int i = 0; i < 8; ++i)
#pragma unroll
        for (int j = 0; j < 8; ++j) acc[i][j] = 0.0f;

    float4 a0 = *(const float4*)(Aptr + 0);
    float4 a1 = *(const float4*)(Aptr + 4);
    float4 b0 = *(const float4*)(Wptr + 0);
    float4 b1 = *(const float4*)(Wptr + 4);

    {
        float av[8] = {a0.x,a0.y,a0.z,a0.w,a1.x,a1.y,a1.z,a1.w};
#pragma unroll
        for (int j = 0; j < 8; ++j) As[(akq + j) * XS + arow] = av[j];
        *(float4*)&Bs[bk * XS + bn]     = b0;
        *(float4*)&Bs[bk * XS + bn + 4] = b1;
    }
    __syncthreads();

    for (int kt = 0; kt < 32; ++kt) {
        const int k_next = (kt + 1) << 4;
        if (kt < 31) {                      // prefetch next tile into regs
            a0 = *(const float4*)(Aptr + k_next + 0);
            a1 = *(const float4*)(Aptr + k_next + 4);
            b0 = *(const float4*)(Wptr + (size_t)k_next * NG + 0);
            b1 = *(const float4*)(Wptr + (size_t)k_next * NG + 4);
        }

#pragma unroll
        for (int kk = 0; kk < 16; ++kk) {
            float4 av0 = *(const float4*)&As[kk * XS + ty * 8];
            float4 av1 = *(const float4*)&As[kk * XS + ty * 8 + 4];
            float4 bv0 = *(const float4*)&Bs[kk * XS + tx * 8];
            float4 bv1 = *(const float4*)&Bs[kk * XS + tx * 8 + 4];
            float aa[8]  = {av0.x,av0.y,av0.z,av0.w,av1.x,av1.y,av1.z,av1.w};
            float bb2[8] = {bv0.x,bv0.y,bv0.z,bv0.w,bv1.x,bv1.y,bv1.z,bv1.w};
#pragma unroll
            for (int i = 0; i < 8; ++i)
#pragma unroll
                for (int j = 0; j < 8; ++j)
                    acc[i][j] = fmaf(aa[i], bb2[j], acc[i][j]);
        }

        if (kt < 31) {
            __syncthreads();
            float av[8] = {a0.x,a0.y,a0.z,a0.w,a1.x,a1.y,a1.z,a1.w};
#pragma unroll
            for (int j = 0; j < 8; ++j) As[(akq + j) * XS + arow] = av[j];
            *(float4*)&Bs[bk * XS + bn]     = b0;
            *(float4*)&Bs[bk * XS + bn + 4] = b1;
            __syncthreads();
        }
    }

    float* __restrict__ Cd = g_xg + (size_t)dir * BB * TT * NG;
    const int nbase = n0 + tx * 8;
    float4 bi0 = *(const float4*)(bias + nbase);
    float4 bi1 = *(const float4*)(bias + nbase + 4);
#pragma unroll
    for (int i = 0; i < 8; ++i) {
        const int m = m0 + ty * 8 + i;
        float4 o0, o1;
        o0.x = acc[i][0] + bi0.x; o0.y = acc[i][1] + bi0.y;
        o0.z = acc[i][2] + bi0.z; o0.w = acc[i][3] + bi0.w;
        o1.x = acc[i][4] + bi1.x; o1.y = acc[i][5] + bi1.y;
        o1.z = acc[i][6] + bi1.z; o1.w = acc[i][7] + bi1.w;
        *(float4*)&Cd[(size_t)m * NG + nbase]     = o0;
        *(float4*)&Cd[(size_t)m * NG + nbase + 4] = o1;
    }
}

// ---------------------------------------------------------------------------
// Software grid barrier: per-direction (64 blocks), monotonic generation.
// All 128 blocks are co-resident (1 block/SM, 128 <= 148 SMs) => no deadlock.
// (EXACT r5 version — best measured; tree variant was 0.9 ms slower.)
// ---------------------------------------------------------------------------
__device__ __forceinline__ void grid_bar(int dir, int tid, unsigned& bar_t)
{
    __syncthreads();
    if (tid == 0) {
        ++bar_t;                           // target generation
        __threadfence();                   // release this block's writes
        unsigned arrived = atomicAdd(&g_cnt[dir], 1u) + 1u;
        if (arrived == 64u) {
            atomicExch(&g_cnt[dir], 0u);
            __threadfence();
            atomicExch(&g_gen[dir], bar_t);
        } else {
            while ((int)(*(volatile unsigned*)&g_gen[dir] - bar_t) < 0) { }
            __threadfence();               // acquire
        }
    }
    __syncthreads();
}

// ---------------------------------------------------------------------------
// Phase 2: persistent scan (EXACT r5 structure — best measured).
// 128 blocks x 256 threads. Block = (dir, 8 cols).
// Per step: zr gates -> g_rh exchange -> barrier -> candidate -> out -> barrier.
// smem: sW 3*512*8 = 12288 | sH 32*513 = 16416 | red 2048  = 30752 floats
// ---------------------------------------------------------------------------
#define SCAN_SMEM_FLOATS (12288 + 16416 + 2048)
#define SCAN_SMEM_BYTES  (SCAN_SMEM_FLOATS * 4)

__global__ void __launch_bounds__(256, 1)
scan_kernel(const float* __restrict__ Uf,
            const float* __restrict__ Ub,
            float* __restrict__ out)
{
    extern __shared__ float sm[];
    float* sW  = sm;             // [g][u][c] : g*4096 + u*8 + c
    float* sH  = sm + 12288;     // [b][u]    : b*513 + u   (h_prev, then rh)
    float* red = sH + 16416;     // reduction scratch

    const int tid   = threadIdx.x;
    const int dir   = blockIdx.x >> 6;
    const int cg    = blockIdx.x & 63;
    const int hbase = cg << 3;
    const float* __restrict__ Urec = dir ? Ub : Uf;

    // --- weight slice, loaded ONCE: sW[g][u][c] = Urec[u][g*512 + hbase + c]
#pragma unroll 4
    for (int i = tid; i < 12288; i += 256) {
        const int c = i & 7;
        const int u = (i >> 3) & 511;
        const int g = i >> 12;
        sW[i] = Urec[(size_t)u * NG + g * UU + hbase + c];
    }

    unsigned bar_t = 0;
    if (tid == 0) bar_t = *(volatile unsigned*)&g_gen[dir];

    // GEMM-thread mapping
    const int ks = tid >> 6;            // 0..3 (K quarter)
    const int bg = (tid >> 3) & 7;      // 0..7 (batch group of 4)
    const int c  = tid & 7;             // 0..7 (column)
    const int u0 = ks << 7;
    // reduce-thread mapping
    const int rb = tid >> 3;            // 0..31 (batch)
    const int rc = tid & 7;             // 0..7  (column)
    const int j  = hbase + rc;

    const float* __restrict__ pw = sW + (u0 << 3) + c;
    const float* __restrict__ h0 = sH + (bg * 4 + 0) * 513 + u0;
    const float* __restrict__ h1 = h0 + 513;
    const float* __restrict__ h2 = h1 + 513;
    const float* __restrict__ h3 = h2 + 513;

    const size_t xg_base = (size_t)dir * BB * TT + (size_t)rb * TT;
    const int    rh_base = (dir * BB) << 9;

    float rz = 0.0f, rzh = 0.0f;        // z and z*h carried A -> B per thread

    for (int s = 0; s < TT; ++s) {
        // prefetch x-gate values (hidden under the FMA loops)
        const int t_x = dir ? (TT - 1 - s) : s;
        const float* __restrict__ xrow = g_xg + (xg_base + t_x) * NG;
        const float xz = xrow[j];
        const float xr = xrow[UU + j];
        const float xh = xrow[2 * UU + j];

        // ---- load h_prev into sH (L2 only: other blocks wrote it) ----
        if (s == 0) {
            for (int i = tid; i < 16416; i += 256) sH[i] = 0.0f;
        } else {
            const float* __restrict__ hp_base =
                out + (size_t)(s - 1) * OC + (size_t)dir * UU;
#pragma unroll 4
            for (int i = tid; i < 4096; i += 256) {
                const int b  = i >> 7;
                const int u4 = (i & 127) << 2;
                float4 v = __ldcg((const float4*)(hp_base + (size_t)b * TT * OC + u4));
                float* d = sH + b * 513 + u4;
                d[0] = v.x; d[1] = v.y; d[2] = v.z; d[3] = v.w;
            }
        }
        __syncthreads();

        // ---- phase A: z/r gate GEMM ----
        float az0 = 0.f, az1 = 0.f, az2 = 0.f, az3 = 0.f;
        float ar0 = 0.f, ar1 = 0.f, ar2 = 0.f, ar3 = 0.f;
#pragma unroll 8
        for (int uu = 0; uu < 128; ++uu) {
            const float wz = pw[uu * 8];
            const float wr = pw[uu * 8 + 4096];
            const float v0 = h0[uu];
            const float v1 = h1[uu];
            const float v2 = h2[uu];
            const float v3 = h3[uu];
            az0 = fmaf(v0, wz, az0); ar0 = fmaf(v0, wr, ar0);
            az1 = fmaf(v1, wz, az1); ar1 = fmaf(v1, wr, ar1);
            az2 = fmaf(v2, wz, az2); ar2 = fmaf(v2, wr, ar2);
            az3 = fmaf(v3, wz, az3); ar3 = fmaf(v3, wr, ar3);
        }
        {
            float* rp = red + ks * 512 + (bg * 4) * 16 + c;
            rp[0]  = az0; rp[8]  = ar0;
            rp[16] = az1; rp[24] = ar1;
            rp[32] = az2; rp[40] = ar2;
            rp[48] = az3; rp[56] = ar3;
        }
        __syncthreads();
        {
            const float* rr = red + rb * 16 + rc;
            const float hz = rr[0] + rr[512] + rr[1024] + rr[1536];
            const float hr = rr[8] + rr[520] + rr[1032] + rr[1544];
            const float z  = hsig(xz + hz);
            const float r  = hsig(xr + hr);
            const float hp = sH[rb * 513 + j];
            rz  = z;
            rzh = z * hp;
            g_rh[rh_base + (rb << 9) + j] = r * hp;
        }
        grid_bar(dir, tid, bar_t);

        // ---- load rh into sH (overwrite; L2 only) ----
#pragma unroll 4
        for (int i = tid; i < 4096; i += 256) {
            const int b  = i >> 7;
            const int u4 = (i & 127) << 2;
            float4 v = __ldcg((const float4*)(g_rh + rh_base + (b << 9) + u4));
            float* d = sH + b * 513 + u4;
            d[0] = v.x; d[1] = v.y; d[2] = v.z; d[3] = v.w;
        }
        __syncthreads();

        // ---- phase B: candidate GEMM (Uh at sW offset 8192) ----
        float ah0 = 0.f, ah1 = 0.f, ah2 = 0.f, ah3 = 0.f;
#pragma unroll 8
        for (int uu = 0; uu < 128; ++uu) {
            const float wh = pw[uu * 8 + 8192];
            ah0 = fmaf(h0[uu], wh, ah0);
            ah1 = fmaf(h1[uu], wh, ah1);
            ah2 = fmaf(h2[uu], wh, ah2);
            ah3 = fmaf(h3[uu], wh, ah3);
        }
        {
            float* rp = red + ks * 256 + (bg * 4) * 8 + c;
            rp[0]  = ah0;
            rp[8]  = ah1;
            rp[16] = ah2;
            rp[24] = ah3;
        }
        __syncthreads();
        {
            const float* rr = red + rb * 8 + rc;
            const float hh   = rr[0] + rr[256] + rr[512] + rr[768];
            const float cand = tanhf(xh + hh);
            const float hnew = rzh + (1.0f - rz) * cand;
            out[((size_t)rb * TT + s) * OC + (size_t)dir * UU + j] = hnew;
        }
        grid_bar(dir, tid, bar_t);
    }
}

// ---------------------------------------------------------------------------
extern "C" void kernel_launch(void* const* d_in, const int* in_sizes, int n_in,
                              void* d_out, int out_size)
{
    (void)in_sizes; (void)n_in; (void)out_size;
    const float* x  = (const float*)d_in[0];
    const float* Wf = (const float*)d_in[1];
    const float* Uf = (const float*)d_in[2];
    const float* bf = (const float*)d_in[3];
    const float* Wb = (const float*)d_in[4];
    const float* Ub = (const float*)d_in[5];
    const float* bb = (const float*)d_in[6];
    float* out = (float*)d_out;

    cudaFuncSetAttribute(scan_kernel,
                         cudaFuncAttributeMaxDynamicSharedMemorySize,
                         SCAN_SMEM_BYTES);

    dim3 g1(NG / 128, (BB * TT) / 128, 2);   // 12 x 128 x 2
    xgemm_kernel<<<g1, 256>>>(x, Wf, bf, Wb, bb);

    scan_kernel<<<128, 256, SCAN_SMEM_BYTES>>>(Uf, Ub, out);
}

// round 13
// speedup vs baseline: 1.3229x; 1.0286x over previous
#include <cuda_runtime.h>

#define BB 32
#define TT 512
#define UU 512
#define NG 1536          // 3*U
#define OC 1024          // 2*U output channels

// x-gates scratch: [dir][B*T][3U] fp32 (192 MB, static device allocation)
__device__ float    g_xg[(size_t)2 * BB * TT * NG];
// per-step rh = r * h_prev exchange buffer
__device__ float    g_rh[2 * BB * UU];
// software grid barrier state (per direction)
__device__ unsigned g_cnt[2];
__device__ unsigned g_gen[2];

__device__ __forceinline__ float hsig(float v) {
    return fminf(fmaxf(0.2f * v + 0.5f, 0.0f), 1.0f);
}

// ---------------------------------------------------------------------------
// Phase 1: Xg[dir][m][n] = x[m][:] @ W_dir[:][n] + bias_dir[n]
// M=16384, K=512, N=1536. BM=BN=128, BK=16, 256 thr, 8x8 reg tile,
// register-prefetch double buffering. (isolated win, kept from r12)
// ---------------------------------------------------------------------------
#define XS 132           // padded smem row stride (floats)

__global__ void __launch_bounds__(256, 2)
xgemm_kernel(const float* __restrict__ A,
             const float* __restrict__ Wf, const float* __restrict__ bf,
             const float* __restrict__ Wb, const float* __restrict__ bb)
{
    const int dir = blockIdx.z;
    const float* __restrict__ W    = dir ? Wb : Wf;
    const float* __restrict__ bias = dir ? bb : bf;
    const int m0 = blockIdx.y * 128;
    const int n0 = blockIdx.x * 128;

    __shared__ float As[16 * XS];   // [k][m]
    __shared__ float Bs[16 * XS];   // [k][n]

    const int tid = threadIdx.x;
    const int tx = tid & 15;        // n group (8 cols)
    const int ty = tid >> 4;        // m group (8 rows)

    const int arow = tid >> 1;             // 0..127
    const int akq  = (tid & 1) << 3;       // 0 or 8
    const int bk = tid >> 4;               // 0..15
    const int bn = (tid & 15) << 3;        // 0..120

    const float* Aptr = A + (size_t)(m0 + arow) * 512 + akq;
    const float* Wptr = W + (size_t)bk * NG + n0 + bn;

    float acc[8][8];
#pragma unroll
    for (int i = 0; i < 8; ++i)
#pragma unroll
        for (int j = 0; j < 8; ++j) acc[i][j] = 0.0f;

    float4 a0 = *(const float4*)(Aptr + 0);
    float4 a1 = *(const float4*)(Aptr + 4);
    float4 b0 = *(const float4*)(Wptr + 0);
    float4 b1 = *(const float4*)(Wptr + 4);

    {
        float av[8] = {a0.x,a0.y,a0.z,a0.w,a1.x,a1.y,a1.z,a1.w};
#pragma unroll
        for (int j = 0; j < 8; ++j) As[(akq + j) * XS + arow] = av[j];
        *(float4*)&Bs[bk * XS + bn]     = b0;
        *(float4*)&Bs[bk * XS + bn + 4] = b1;
    }
    __syncthreads();

    for (int kt = 0; kt < 32; ++kt) {
        const int k_next = (kt + 1) << 4;
        if (kt < 31) {                      // prefetch next tile into regs
            a0 = *(const float4*)(Aptr + k_next + 0);
            a1 = *(const float4*)(Aptr + k_next + 4);
            b0 = *(const float4*)(Wptr + (size_t)k_next * NG + 0);
            b1 = *(const float4*)(Wptr + (size_t)k_next * NG + 4);
        }

#pragma unroll
        for (int kk = 0; kk < 16; ++kk) {
            float4 av0 = *(const float4*)&As[kk * XS + ty * 8];
            float4 av1 = *(const float4*)&As[kk * XS + ty * 8 + 4];
            float4 bv0 = *(const float4*)&Bs[kk * XS + tx * 8];
            float4 bv1 = *(const float4*)&Bs[kk * XS + tx * 8 + 4];
            float aa[8]  = {av0.x,av0.y,av0.z,av0.w,av1.x,av1.y,av1.z,av1.w};
            float bb2[8] = {bv0.x,bv0.y,bv0.z,bv0.w,bv1.x,bv1.y,bv1.z,bv1.w};
#pragma unroll
            for (int i = 0; i < 8; ++i)
#pragma unroll
                for (int j = 0; j < 8; ++j)
                    acc[i][j] = fmaf(aa[i], bb2[j], acc[i][j]);
        }

        if (kt < 31) {
            __syncthreads();
            float av[8] = {a0.x,a0.y,a0.z,a0.w,a1.x,a1.y,a1.z,a1.w};
#pragma unroll
            for (int j = 0; j < 8; ++j) As[(akq + j) * XS + arow] = av[j];
            *(float4*)&Bs[bk * XS + bn]     = b0;
            *(float4*)&Bs[bk * XS + bn + 4] = b1;
            __syncthreads();
        }
    }

    float* __restrict__ Cd = g_xg + (size_t)dir * BB * TT * NG;
    const int nbase = n0 + tx * 8;
    float4 bi0 = *(const float4*)(bias + nbase);
    float4 bi1 = *(const float4*)(bias + nbase + 4);
#pragma unroll
    for (int i = 0; i < 8; ++i) {
        const int m = m0 + ty * 8 + i;
        float4 o0, o1;
        o0.x = acc[i][0] + bi0.x; o0.y = acc[i][1] + bi0.y;
        o0.z = acc[i][2] + bi0.z; o0.w = acc[i][3] + bi0.w;
        o1.x = acc[i][4] + bi1.x; o1.y = acc[i][5] + bi1.y;
        o1.z = acc[i][6] + bi1.z; o1.w = acc[i][7] + bi1.w;
        *(float4*)&Cd[(size_t)m * NG + nbase]     = o0;
        *(float4*)&Cd[(size_t)m * NG + nbase + 4] = o1;
    }
}

// ---------------------------------------------------------------------------
// Software grid barrier: per-direction (64 blocks), monotonic generation.
// (EXACT r5/r12 version — best measured.)
// ---------------------------------------------------------------------------
__device__ __forceinline__ void grid_bar(int dir, int tid, unsigned& bar_t)
{
    __syncthreads();
    if (tid == 0) {
        ++bar_t;                           // target generation
        __threadfence();                   // release this block's writes
        unsigned arrived = atomicAdd(&g_cnt[dir], 1u) + 1u;
        if (arrived == 64u) {
            atomicExch(&g_cnt[dir], 0u);
            __threadfence();
            atomicExch(&g_gen[dir], bar_t);
        } else {
            while ((int)(*(volatile unsigned*)&g_gen[dir] - bar_t) < 0) { }
            __threadfence();               // acquire
        }
    }
    __syncthreads();
}

// ---------------------------------------------------------------------------
// Phase 2: persistent scan — r12 structure, 512 threads/block (ONLY change).
// 128 blocks x 512 threads. Block = (dir, 8 cols). 16 warps/SM for latency
// hiding; K split 8-ways per thread (u0 = ks*64), 8-way smem reduction.
// smem: sW 12288 | sH 16416 | red 4096  = 32800 floats = 131,200 B
// ---------------------------------------------------------------------------
#define SCAN_SMEM_FLOATS (12288 + 16416 + 4096)
#define SCAN_SMEM_BYTES  (SCAN_SMEM_FLOATS * 4)

__global__ void __launch_bounds__(512, 1)
scan_kernel(const float* __restrict__ Uf,
            const float* __restrict__ Ub,
            float* __restrict__ out)
{
    extern __shared__ float sm[];
    float* sW  = sm;             // [g][u][c] : g*4096 + u*8 + c
    float* sH  = sm + 12288;     // [b][u]    : b*513 + u   (h_prev, then rh)
    float* red = sH + 16416;     // reduction scratch (8-way)

    const int tid   = threadIdx.x;
    const int dir   = blockIdx.x >> 6;
    const int cg    = blockIdx.x & 63;
    const int hbase = cg << 3;
    const float* __restrict__ Urec = dir ? Ub : Uf;

    // --- weight slice, loaded ONCE: sW[g][u][c] = Urec[u][g*512 + hbase + c]
#pragma unroll 4
    for (int i = tid; i < 12288; i += 512) {
        const int c = i & 7;
        const int u = (i >> 3) & 511;
        const int g = i >> 12;
        sW[i] = Urec[(size_t)u * NG + g * UU + hbase + c];
    }

    unsigned bar_t = 0;
    if (tid == 0) bar_t = *(volatile unsigned*)&g_gen[dir];

    // GEMM-thread mapping: 8 K-eighths x 8 batch-groups(4 batches) x 8 cols
    const int ks = tid >> 6;            // 0..7 (K eighth)
    const int bg = (tid >> 3) & 7;      // 0..7 (batch group of 4)
    const int c  = tid & 7;             // 0..7 (column)
    const int u0 = ks << 6;             // 0,64,...,448
    // reduce-thread mapping (tid < 256 active)
    const int rb = (tid >> 3) & 31;     // 0..31 (batch)
    const int rc = tid & 7;             // 0..7  (column)
    const int j  = hbase + rc;

    const float* __restrict__ pw = sW + (u0 << 3) + c;
    const float* __restrict__ h0 = sH + (bg * 4 + 0) * 513 + u0;
    const float* __restrict__ h1 = h0 + 513;
    const float* __restrict__ h2 = h1 + 513;
    const float* __restrict__ h3 = h2 + 513;

    const size_t xg_base = (size_t)dir * BB * TT + (size_t)rb * TT;
    const int    rh_base = (dir * BB) << 9;

    float rz = 0.0f, rzh = 0.0f;        // carried A -> B (tid < 256 only)

    for (int s = 0; s < TT; ++s) {
        // prefetch x-gate values (tid < 256 only; hidden under FMA loops)
        const int t_x = dir ? (TT - 1 - s) : s;
        const float* __restrict__ xrow = g_xg + (xg_base + t_x) * NG;
        float xz = 0.f, xr = 0.f, xh = 0.f;
        if (tid < 256) {
            xz = xrow[j];
            xr = xrow[UU + j];
            xh = xrow[2 * UU + j];
        }

        // ---- load h_prev into sH (L2 only; 8 float4/thread) ----
        if (s == 0) {
            for (int i = tid; i < 16416; i += 512) sH[i] = 0.0f;
        } else {
            const float* __restrict__ hp_base =
                out + (size_t)(s - 1) * OC + (size_t)dir * UU;
#pragma unroll 8
            for (int i = tid; i < 4096; i += 512) {
                const int b  = i >> 7;
                const int u4 = (i & 127) << 2;
                float4 v = __ldcg((const float4*)(hp_base + (size_t)b * TT * OC + u4));
                float* d = sH + b * 513 + u4;
                d[0] = v.x; d[1] = v.y; d[2] = v.z; d[3] = v.w;
            }
        }
        __syncthreads();

        // ---- phase A: z/r gate GEMM over K eighth (64 u) ----
        float az0 = 0.f, az1 = 0.f, az2 = 0.f, az3 = 0.f;
        float ar0 = 0.f, ar1 = 0.f, ar2 = 0.f, ar3 = 0.f;
#pragma unroll 8
        for (int uu = 0; uu < 64; ++uu) {
            const float wz = pw[uu * 8];
            const float wr = pw[uu * 8 + 4096];
            const float v0 = h0[uu];
            const float v1 = h1[uu];
            const float v2 = h2[uu];
            const float v3 = h3[uu];
            az0 = fmaf(v0, wz, az0); ar0 = fmaf(v0, wr, ar0);
            az1 = fmaf(v1, wz, az1); ar1 = fmaf(v1, wr, ar1);
            az2 = fmaf(v2, wz, az2); ar2 = fmaf(v2, wr, ar2);
            az3 = fmaf(v3, wz, az3); ar3 = fmaf(v3, wr, ar3);
        }
        {
            float* rp = red + ks * 512 + (bg * 4) * 16 + c;
            rp[0]  = az0; rp[8]  = ar0;
            rp[16] = az1; rp[24] = ar1;
            rp[32] = az2; rp[40] = ar2;
            rp[48] = az3; rp[56] = ar3;
        }
        __syncthreads();
        if (tid < 256) {
            const float* rr = red + rb * 16 + rc;
            float hz = 0.f, hr = 0.f;
#pragma unroll
            for (int k = 0; k < 8; ++k) {
                hz += rr[k * 512];
                hr += rr[k * 512 + 8];
            }
            const float z  = hsig(xz + hz);
            const float r  = hsig(xr + hr);
            const float hp = sH[rb * 513 + j];
            rz  = z;
            rzh = z * hp;
            g_rh[rh_base + (rb << 9) + j] = r * hp;
        }
        grid_bar(dir, tid, bar_t);

        // ---- load rh into sH (overwrite; L2 only; 8 float4/thread) ----
#pragma unroll 8
        for (int i = tid; i < 4096; i += 512) {
            const int b  = i >> 7;
            const int u4 = (i & 127) << 2;
            float4 v = __ldcg((const float4*)(g_rh + rh_base + (b << 9) + u4));
            float* d = sH + b * 513 + u4;
            d[0] = v.x; d[1] = v.y; d[2] = v.z; d[3] = v.w;
        }
        __syncthreads();

        // ---- phase B: candidate GEMM (Uh at sW offset 8192) ----
        float ah0 = 0.f, ah1 = 0.f, ah2 = 0.f, ah3 = 0.f;
#pragma unroll 8
        for (int uu = 0; uu < 64; ++uu) {
            const float wh = pw[uu * 8 + 8192];
            ah0 = fmaf(h0[uu], wh, ah0);
            ah1 = fmaf(h1[uu], wh, ah1);
            ah2 = fmaf(h2[uu], wh, ah2);
            ah3 = fmaf(h3[uu], wh, ah3);
        }
        {
            float* rp = red + ks * 256 + (bg * 4) * 8 + c;
            rp[0]  = ah0;
            rp[8]  = ah1;
            rp[16] = ah2;
            rp[24] = ah3;
        }
        __syncthreads();
        if (tid < 256) {
            const float* rr = red + rb * 8 + rc;
            float hh = 0.f;
#pragma unroll
            for (int k = 0; k < 8; ++k) hh += rr[k * 256];
            const float cand = tanhf(xh + hh);
            const float hnew = rzh + (1.0f - rz) * cand;
            out[((size_t)rb * TT + s) * OC + (size_t)dir * UU + j] = hnew;
        }
        grid_bar(dir, tid, bar_t);
    }
}

// ---------------------------------------------------------------------------
extern "C" void kernel_launch(void* const* d_in, const int* in_sizes, int n_in,
                              void* d_out, int out_size)
{
    (void)in_sizes; (void)n_in; (void)out_size;
    const float* x  = (const float*)d_in[0];
    const float* Wf = (const float*)d_in[1];
    const float* Uf = (const float*)d_in[2];
    const float* bf = (const float*)d_in[3];
    const float* Wb = (const float*)d_in[4];
    const float* Ub = (const float*)d_in[5];
    const float* bb = (const float*)d_in[6];
    float* out = (float*)d_out;

    cudaFuncSetAttribute(scan_kernel,
                         cudaFuncAttributeMaxDynamicSharedMemorySize,
                         SCAN_SMEM_BYTES);

    dim3 g1(NG / 128, (BB * TT) / 128, 2);   // 12 x 128 x 2
    xgemm_kernel<<<g1, 256>>>(x, Wf, bf, Wb, bb);

    scan_kernel<<<128, 512, SCAN_SMEM_BYTES>>>(Uf, Ub, out);
}

// round 14
// speedup vs baseline: 1.3744x; 1.0389x over previous
#include <cuda_runtime.h>

#define BB 32
#define TT 512
#define UU 512
#define NG 1536          // 3*U
#define OC 1024          // 2*U output channels

// x-gates scratch: [dir][B*T][3U] fp32 (192 MB, static device allocation)
__device__ float    g_xg[(size_t)2 * BB * TT * NG];
// per-step rh = r * h_prev exchange buffer
__device__ float    g_rh[2 * BB * UU];
// per-step split barriers (reset at kernel end, replay-safe)
__device__ int      g_bar1[2 * TT];
__device__ int      g_bar2[2 * TT];
__device__ int      g_done;

__device__ __forceinline__ float hsig(float v) {
    return fminf(fmaxf(0.2f * v + 0.5f, 0.0f), 1.0f);
}

// ---------------------------------------------------------------------------
// Phase 1: Xg[dir][m][n] = x[m][:] @ W_dir[:][n] + bias_dir[n]
// M=16384, K=512, N=1536. BM=BN=128, BK=16, 256 thr, 8x8 reg tile,
// register-prefetch double buffering. (isolated win, kept from r12/r13)
// ---------------------------------------------------------------------------
#define XS 132           // padded smem row stride (floats)

__global__ void __launch_bounds__(256, 2)
xgemm_kernel(const float* __restrict__ A,
             const float* __restrict__ Wf, const float* __restrict__ bf,
             const float* __restrict__ Wb, const float* __restrict__ bb)
{
    const int dir = blockIdx.z;
    const float* __restrict__ W    = dir ? Wb : Wf;
    const float* __restrict__ bias = dir ? bb : bf;
    const int m0 = blockIdx.y * 128;
    const int n0 = blockIdx.x * 128;

    __shared__ float As[16 * XS];   // [k][m]
    __shared__ float Bs[16 * XS];   // [k][n]

    const int tid = threadIdx.x;
    const int tx = tid & 15;        // n group (8 cols)
    const int ty = tid >> 4;        // m group (8 rows)

    const int arow = tid >> 1;             // 0..127
    const int akq  = (tid & 1) << 3;       // 0 or 8
    const int bk = tid >> 4;               // 0..15
    const int bn = (tid & 15) << 3;        // 0..120

    const float* Aptr = A + (size_t)(m0 + arow) * 512 + akq;
    const float* Wptr = W + (size_t)bk * NG + n0 + bn;

    float acc[8][8];
#pragma unroll
    for (int i = 0; i < 8; ++i)
#pragma unroll
        for (int j = 0; j < 8; ++j) acc[i][j] = 0.0f;

    float4 a0 = *(const float4*)(Aptr + 0);
    float4 a1 = *(const float4*)(Aptr + 4);
    float4 b0 = *(const float4*)(Wptr + 0);
    float4 b1 = *(const float4*)(Wptr + 4);

    {
        float av[8] = {a0.x,a0.y,a0.z,a0.w,a1.x,a1.y,a1.z,a1.w};
#pragma unroll
        for (int j = 0; j < 8; ++j) As[(akq + j) * XS + arow] = av[j];
        *(float4*)&Bs[bk * XS + bn]     = b0;
        *(float4*)&Bs[bk * XS + bn + 4] = b1;
    }
    __syncthreads();

    for (int kt = 0; kt < 32; ++kt) {
        const int k_next = (kt + 1) << 4;
        if (kt < 31) {                      // prefetch next tile into regs
            a0 = *(const float4*)(Aptr + k_next + 0);
            a1 = *(const float4*)(Aptr + k_next + 4);
            b0 = *(const float4*)(Wptr + (size_t)k_next * NG + 0);
            b1 = *(const float4*)(Wptr + (size_t)k_next * NG + 4);
        }

#pragma unroll
        for (int kk = 0; kk < 16; ++kk) {
            float4 av0 = *(const float4*)&As[kk * XS + ty * 8];
            float4 av1 = *(const float4*)&As[kk * XS + ty * 8 + 4];
            float4 bv0 = *(const float4*)&Bs[kk * XS + tx * 8];
            float4 bv1 = *(const float4*)&Bs[kk * XS + tx * 8 + 4];
            float aa[8]  = {av0.x,av0.y,av0.z,av0.w,av1.x,av1.y,av1.z,av1.w};
            float bb2[8] = {bv0.x,bv0.y,bv0.z,bv0.w,bv1.x,bv1.y,bv1.z,bv1.w};
#pragma unroll
            for (int i = 0; i < 8; ++i)
#pragma unroll
                for (int j = 0; j < 8; ++j)
                    acc[i][j] = fmaf(aa[i], bb2[j], acc[i][j]);
        }

        if (kt < 31) {
            __syncthreads();
            float av[8] = {a0.x,a0.y,a0.z,a0.w,a1.x,a1.y,a1.z,a1.w};
#pragma unroll
            for (int j = 0; j < 8; ++j) As[(akq + j) * XS + arow] = av[j];
            *(float4*)&Bs[bk * XS + bn]     = b0;
            *(float4*)&Bs[bk * XS + bn + 4] = b1;
            __syncthreads();
        }
    }

    float* __restrict__ Cd = g_xg + (size_t)dir * BB * TT * NG;
    const int nbase = n0 + tx * 8;
    float4 bi0 = *(const float4*)(bias + nbase);
    float4 bi1 = *(const float4*)(bias + nbase + 4);
#pragma unroll
    for (int i = 0; i < 8; ++i) {
        const int m = m0 + ty * 8 + i;
        float4 o0, o1;
        o0.x = acc[i][0] + bi0.x; o0.y = acc[i][1] + bi0.y;
        o0.z = acc[i][2] + bi0.z; o0.w = acc[i][3] + bi0.w;
        o1.x = acc[i][4] + bi1.x; o1.y = acc[i][5] + bi1.y;
        o1.z = acc[i][6] + bi1.z; o1.w = acc[i][7] + bi1.w;
        *(float4*)&Cd[(size_t)m * NG + nbase]     = o0;
        *(float4*)&Cd[(size_t)m * NG + nbase + 4] = o1;
    }
}

// ---------------------------------------------------------------------------
// Per-step split barrier helpers (64 arrivals per direction per step).
// ---------------------------------------------------------------------------
__device__ __forceinline__ void bar_arrive(int* cnt, int tid)
{
    __threadfence();                 // release: my global writes visible
    __syncthreads();                 // all threads of block have fenced
    if (tid == 0) atomicAdd(cnt, 1);
}

__device__ __forceinline__ void bar_wait(int* cnt, int tid)
{
    if (tid == 0) {
        while (*(volatile int*)cnt < 64) { }
        __threadfence();             // acquire
    }
    __syncthreads();
}

// ---------------------------------------------------------------------------
// Phase 2: persistent scan — r13 base (512 thr, 128 blocks, scalar loops);
// ONLY change: phase A split into r-gate -> publish rh -> arrive(bar1)
// -> z-gate (overlaps barrier) -> wait(bar1).
// smem: sW 12288 | sH 16416 | red 2048  = 30752 floats = 123,008 B
// ---------------------------------------------------------------------------
#define SCAN_SMEM_FLOATS (12288 + 16416 + 2048)
#define SCAN_SMEM_BYTES  (SCAN_SMEM_FLOATS * 4)

__global__ void __launch_bounds__(512, 1)
scan_kernel(const float* __restrict__ Uf,
            const float* __restrict__ Ub,
            float* __restrict__ out)
{
    extern __shared__ float sm[];
    float* sW  = sm;             // [g][u][c] : g*4096 + u*8 + c
    float* sH  = sm + 12288;     // [b][u]    : b*513 + u   (h_prev, then rh)
    float* red = sH + 16416;     // 8 ks x 32 b x 8 c = 2048 floats

    const int tid   = threadIdx.x;
    const int dir   = blockIdx.x >> 6;
    const int cg    = blockIdx.x & 63;
    const int hbase = cg << 3;
    const float* __restrict__ Urec = dir ? Ub : Uf;

    // --- weight slice, loaded ONCE: sW[g][u][c] = Urec[u][g*512 + hbase + c]
#pragma unroll 4
    for (int i = tid; i < 12288; i += 512) {
        const int c = i & 7;
        const int u = (i >> 3) & 511;
        const int g = i >> 12;
        sW[i] = Urec[(size_t)u * NG + g * UU + hbase + c];
    }

    // GEMM-thread mapping: 8 K-eighths x 8 batch-groups(4) x 8 cols
    const int ks = tid >> 6;            // 0..7
    const int bg = (tid >> 3) & 7;      // 0..7
    const int c  = tid & 7;             // 0..7
    const int u0 = ks << 6;             // 0,64,...,448
    // reduce-thread mapping (tid < 256 active)
    const int rb = (tid >> 3) & 31;     // 0..31
    const int rc = tid & 7;             // 0..7
    const int j  = hbase + rc;

    const float* __restrict__ pw = sW + (u0 << 3) + c;
    const float* __restrict__ h0 = sH + (bg * 4 + 0) * 513 + u0;
    const float* __restrict__ h1 = h0 + 513;
    const float* __restrict__ h2 = h1 + 513;
    const float* __restrict__ h3 = h2 + 513;

    const size_t xg_base = (size_t)dir * BB * TT + (size_t)rb * TT;
    const int    rh_base = (dir * BB) << 9;
    int* __restrict__ bar1 = g_bar1 + dir * TT;
    int* __restrict__ bar2 = g_bar2 + dir * TT;

    __syncthreads();                     // weights ready

    for (int s = 0; s < TT; ++s) {
        // prefetch x-gate values (tid < 256; hidden under FMA loops)
        const int t_x = dir ? (TT - 1 - s) : s;
        const float* __restrict__ xrow = g_xg + (xg_base + t_x) * NG;
        float xz = 0.f, xr = 0.f, xh = 0.f;
        if (tid < 256) {
            xz = xrow[j];
            xr = xrow[UU + j];
            xh = xrow[2 * UU + j];
        }

        // ---- load h_prev into sH (L2 only; 8 float4/thread) ----
        if (s == 0) {
            for (int i = tid; i < 16416; i += 512) sH[i] = 0.0f;
        } else {
            const float* __restrict__ hp_base =
                out + (size_t)(s - 1) * OC + (size_t)dir * UU;
#pragma unroll 8
            for (int i = tid; i < 4096; i += 512) {
                const int b  = i >> 7;
                const int u4 = (i & 127) << 2;
                float4 v = __ldcg((const float4*)(hp_base + (size_t)b * TT * OC + u4));
                float* d = sH + b * 513 + u4;
                d[0] = v.x; d[1] = v.y; d[2] = v.z; d[3] = v.w;
            }
        }
        __syncthreads();

        // own h_prev element, before sH is later overwritten by rh
        float hp = 0.0f;
        if (tid < 256) hp = sH[rb * 513 + j];

        // ---- phase A-r: r-gate GEMM over K eighth (64 u) ----
        float ar0 = 0.f, ar1 = 0.f, ar2 = 0.f, ar3 = 0.f;
#pragma unroll 8
        for (int uu = 0; uu < 64; ++uu) {
            const float wr = pw[uu * 8 + 4096];
            ar0 = fmaf(h0[uu], wr, ar0);
            ar1 = fmaf(h1[uu], wr, ar1);
            ar2 = fmaf(h2[uu], wr, ar2);
            ar3 = fmaf(h3[uu], wr, ar3);
        }
        {
            float* rp = red + ks * 256 + (bg * 4) * 8 + c;
            rp[0]  = ar0;
            rp[8]  = ar1;
            rp[16] = ar2;
            rp[24] = ar3;
        }
        __syncthreads();
        if (tid < 256) {
            const float* rr = red + rb * 8 + rc;
            float hr = 0.f;
#pragma unroll
            for (int k = 0; k < 8; ++k) hr += rr[k * 256];
            const float r = hsig(xr + hr);
            g_rh[rh_base + (rb << 9) + j] = r * hp;
        }
        bar_arrive(&bar1[s], tid);       // rh published; others may proceed

        // ---- phase A-z: z-gate GEMM (overlaps other blocks' arrivals) ----
        float az0 = 0.f, az1 = 0.f, az2 = 0.f, az3 = 0.f;
#pragma unroll 8
        for (int uu = 0; uu < 64; ++uu) {
            const float wz = pw[uu * 8];
            az0 = fmaf(h0[uu], wz, az0);
            az1 = fmaf(h1[uu], wz, az1);
            az2 = fmaf(h2[uu], wz, az2);
            az3 = fmaf(h3[uu], wz, az3);
        }
        {
            float* rp = red + ks * 256 + (bg * 4) * 8 + c;
            rp[0]  = az0;
            rp[8]  = az1;
            rp[16] = az2;
            rp[24] = az3;
        }
        __syncthreads();
        float rz = 0.0f, rzh = 0.0f;
        if (tid < 256) {
            const float* rr = red + rb * 8 + rc;
            float hz = 0.f;
#pragma unroll
            for (int k = 0; k < 8; ++k) hz += rr[k * 256];
            const float z = hsig(xz + hz);
            rz  = z;
            rzh = z * hp;
        }
        bar_wait(&bar1[s], tid);         // should be nearly free now

        // ---- load rh into sH (overwrite; L2 only; 8 float4/thread) ----
#pragma unroll 8
        for (int i = tid; i < 4096; i += 512) {
            const int b  = i >> 7;
            const int u4 = (i & 127) << 2;
            float4 v = __ldcg((const float4*)(g_rh + rh_base + (b << 9) + u4));
            float* d = sH + b * 513 + u4;
            d[0] = v.x; d[1] = v.y; d[2] = v.z; d[3] = v.w;
        }
        __syncthreads();

        // ---- phase B: candidate GEMM (Uh at sW offset 8192) ----
        float ah0 = 0.f, ah1 = 0.f, ah2 = 0.f, ah3 = 0.f;
#pragma unroll 8
        for (int uu = 0; uu < 64; ++uu) {
            const float wh = pw[uu * 8 + 8192];
            ah0 = fmaf(h0[uu], wh, ah0);
            ah1 = fmaf(h1[uu], wh, ah1);
            ah2 = fmaf(h2[uu], wh, ah2);
            ah3 = fmaf(h3[uu], wh, ah3);
        }
        {
            float* rp = red + ks * 256 + (bg * 4) * 8 + c;
            rp[0]  = ah0;
            rp[8]  = ah1;
            rp[16] = ah2;
            rp[24] = ah3;
        }
        __syncthreads();
        if (tid < 256) {
            const float* rr = red + rb * 8 + rc;
            float hh = 0.f;
#pragma unroll
            for (int k = 0; k < 8; ++k) hh += rr[k * 256];
            const float cand = tanhf(xh + hh);
            const float hnew = rzh + (1.0f - rz) * cand;
            out[((size_t)rb * TT + s) * OC + (size_t)dir * UU + j] = hnew;
        }

        // ---- step closure: h_new visible to all blocks of this direction --
        bar_arrive(&bar2[s], tid);
        bar_wait(&bar2[s], tid);
    }

    // ---- reset per-step counters for next graph replay ----
    __syncthreads();
    if (tid == 0) atomicAdd(&g_done, 1);
    if (blockIdx.x == 0) {
        if (tid == 0) {
            while (*(volatile int*)&g_done < 128) { }
        }
        __syncthreads();
        for (int i = tid; i < 2 * TT; i += 512) {
            g_bar1[i] = 0;
            g_bar2[i] = 0;
        }
        __threadfence();
        __syncthreads();
        if (tid == 0) g_done = 0;
    }
}

// ---------------------------------------------------------------------------
extern "C" void kernel_launch(void* const* d_in, const int* in_sizes, int n_in,
                              void* d_out, int out_size)
{
    (void)in_sizes; (void)n_in; (void)out_size;
    const float* x  = (const float*)d_in[0];
    const float* Wf = (const float*)d_in[1];
    const float* Uf = (const float*)d_in[2];
    const float* bf = (const float*)d_in[3];
    const float* Wb = (const float*)d_in[4];
    const float* Ub = (const float*)d_in[5];
    const float* bb = (const float*)d_in[6];
    float* out = (float*)d_out;

    cudaFuncSetAttribute(scan_kernel,
                         cudaFuncAttributeMaxDynamicSharedMemorySize,
                         SCAN_SMEM_BYTES);

    dim3 g1(NG / 128, (BB * TT) / 128, 2);   // 12 x 128 x 2
    xgemm_kernel<<<g1, 256>>>(x, Wf, bf, Wb, bb);

    scan_kernel<<<128, 512, SCAN_SMEM_BYTES>>>(Uf, Ub, out);
}